// round 4
// baseline (speedup 1.0000x reference)
#include <cuda_runtime.h>

// Problem constants (fixed by the dataset)
constexpr int BB   = 16;     // batch
constexpr int NTOK = 16384;  // tokens
constexpr int DD   = 64;     // model dim (= dhf)
constexpr int GG   = 256;    // groups
constexpr int CC   = 64;     // tokens per group
constexpr int NH   = 4;      // heads
// SCALE = sqrt(16) = 4.0 and it MULTIPLIES the scores (per reference)

#define LDSF 68  // smem row stride in floats (16B-aligned rows, conflict-staggered)

// ---------------- scratch (no allocations allowed) ----------------
__device__ float g_pooled[BB * GG * DD];      // 1 MiB
__device__ float g_qkv[3 * BB * GG * DD];     // 3 MiB  [q/k/v][b][n][d]
__device__ float g_inter[BB * GG * DD];       // 1 MiB

// ---------------- helpers ----------------
__device__ __forceinline__ void stage64(const float* __restrict__ W, float* ws, int tid) {
    // copy 64x64 row-major matrix into smem with LDSF stride; 256 threads
#pragma unroll
    for (int k = 0; k < 4; ++k) {
        int f = tid + 256 * k;      // float4 index 0..1023
        int r = f >> 4, c4 = f & 15;
        *(float4*)&ws[r * LDSF + 4 * c4] = ((const float4*)(W + r * 64))[c4];
    }
}

__device__ __forceinline__ void fma16(float acc[4][4], const float4 a[4], const float4 w[4]) {
#pragma unroll
    for (int i = 0; i < 4; ++i)
#pragma unroll
        for (int j = 0; j < 4; ++j) {
            acc[i][j] = fmaf(a[i].x, w[j].x, acc[i][j]);
            acc[i][j] = fmaf(a[i].y, w[j].y, acc[i][j]);
            acc[i][j] = fmaf(a[i].z, w[j].z, acc[i][j]);
            acc[i][j] = fmaf(a[i].w, w[j].w, acc[i][j]);
        }
}

// ---------------- Kernel 1: intra-group MHA + scatter + pooled-max ----------------
// grid = 4096 (b*256+g), 256 threads, dynamic smem = 5 * 64 * LDSF * 4 bytes
__global__ __launch_bounds__(256, 2) void intra_kernel(
    const float* __restrict__ x, const int* __restrict__ part,
    const float* __restrict__ Wq, const float* __restrict__ bq,
    const float* __restrict__ Wk, const float* __restrict__ bk,
    const float* __restrict__ Wv, const float* __restrict__ bv,
    const float* __restrict__ Wo, const float* __restrict__ bo,
    float* __restrict__ out)
{
    extern __shared__ float sm[];
    float* xs = sm;                 // x, later attention output
    float* qs = sm + 64 * LDSF;     // q, later O-proj result (for pooled max)
    float* ks = sm + 2 * 64 * LDSF;
    float* vs = sm + 3 * 64 * LDSF;
    float* ws = sm + 4 * 64 * LDSF; // weight stage / attention probs

    const int tid = threadIdx.x;
    const int b = blockIdx.x >> 8;
    const int g = blockIdx.x & 255;
    const int* pg = part + (size_t)g * CC;
    const float* xb = x + (size_t)b * NTOK * DD;

    // gather 64 token rows
#pragma unroll
    for (int k = 0; k < 4; ++k) {
        int f = tid + 256 * k;
        int row = f >> 4, c4 = f & 15;
        int tok = pg[row];
        *(float4*)&xs[row * LDSF + 4 * c4] = ((const float4*)(xb + (size_t)tok * DD))[c4];
    }

    const int tn = tid >> 4, to = tid & 15;  // 16x16 thread grid, 4x4 output tiles

    // ---- Q, K, V projections: D = xs @ W^T + b ----
    {
        const float* Wm[3] = {Wq, Wk, Wv};
        const float* bm[3] = {bq, bk, bv};
        float* Dm[3] = {qs, ks, vs};
#pragma unroll
        for (int s = 0; s < 3; ++s) {
            __syncthreads();
            stage64(Wm[s], ws, tid);
            __syncthreads();
            float acc[4][4] = {};
#pragma unroll 4
            for (int d4 = 0; d4 < 64; d4 += 4) {
                float4 a[4], w[4];
#pragma unroll
                for (int i = 0; i < 4; ++i) a[i] = *(const float4*)&xs[(4 * tn + i) * LDSF + d4];
#pragma unroll
                for (int j = 0; j < 4; ++j) w[j] = *(const float4*)&ws[(4 * to + j) * LDSF + d4];
                fma16(acc, a, w);
            }
            float* D = Dm[s];
#pragma unroll
            for (int j = 0; j < 4; ++j) {
                float bj = bm[s][4 * to + j];
#pragma unroll
                for (int i = 0; i < 4; ++i)
                    D[(4 * tn + i) * LDSF + 4 * to + j] = acc[i][j] + bj;
            }
        }
    }

    // ---- attention, head by head (probs live in ws; output into xs) ----
#pragma unroll 1
    for (int h = 0; h < NH; ++h) {
        const int hq = h * 16;
        __syncthreads();  // ws free (prev stage / prev head's AV done)
        // scores s[n][m] = SCALE * q[n,h,:] . k[m,h,:]
        {
            float acc[4][4] = {};
#pragma unroll
            for (int d4 = 0; d4 < 16; d4 += 4) {
                float4 a[4], w[4];
#pragma unroll
                for (int i = 0; i < 4; ++i) a[i] = *(const float4*)&qs[(4 * tn + i) * LDSF + hq + d4];
#pragma unroll
                for (int j = 0; j < 4; ++j) w[j] = *(const float4*)&ks[(4 * to + j) * LDSF + hq + d4];
                fma16(acc, a, w);
            }
#pragma unroll
            for (int i = 0; i < 4; ++i)
#pragma unroll
                for (int j = 0; j < 4; ++j)
                    ws[(4 * tn + i) * LDSF + 4 * to + j] = 4.0f * acc[i][j];
        }
        __syncthreads();
        // softmax: 4 threads per row, quad shuffles
        {
            int row = tid >> 2, seg = tid & 3;
            float* r = ws + row * LDSF + seg * 16;
            float mx = r[0];
#pragma unroll
            for (int m = 1; m < 16; ++m) mx = fmaxf(mx, r[m]);
            mx = fmaxf(mx, __shfl_xor_sync(0xffffffffu, mx, 1));
            mx = fmaxf(mx, __shfl_xor_sync(0xffffffffu, mx, 2));
            float e[16];
            float sum = 0.f;
#pragma unroll
            for (int m = 0; m < 16; ++m) { e[m] = __expf(r[m] - mx); sum += e[m]; }
            sum += __shfl_xor_sync(0xffffffffu, sum, 1);
            sum += __shfl_xor_sync(0xffffffffu, sum, 2);
            float inv = 1.f / sum;
#pragma unroll
            for (int m = 0; m < 16; ++m) r[m] = e[m] * inv;
        }
        __syncthreads();
        // AV: thread (tn,to) -> rows 4tn+i, column dd = to of this head
        {
            float acc2[4] = {0.f, 0.f, 0.f, 0.f};
#pragma unroll 4
            for (int m4 = 0; m4 < 64; m4 += 4) {
                float4 p[4];
#pragma unroll
                for (int i = 0; i < 4; ++i) p[i] = *(const float4*)&ws[(4 * tn + i) * LDSF + m4];
                float v0 = vs[(m4 + 0) * LDSF + hq + to];
                float v1 = vs[(m4 + 1) * LDSF + hq + to];
                float v2 = vs[(m4 + 2) * LDSF + hq + to];
                float v3 = vs[(m4 + 3) * LDSF + hq + to];
#pragma unroll
                for (int i = 0; i < 4; ++i) {
                    acc2[i] = fmaf(p[i].x, v0, acc2[i]);
                    acc2[i] = fmaf(p[i].y, v1, acc2[i]);
                    acc2[i] = fmaf(p[i].z, v2, acc2[i]);
                    acc2[i] = fmaf(p[i].w, v3, acc2[i]);
                }
            }
#pragma unroll
            for (int i = 0; i < 4; ++i) xs[(4 * tn + i) * LDSF + hq + to] = acc2[i];
        }
    }

    // ---- O projection (+bias), scatter to out, pooled max ----
    __syncthreads();
    stage64(Wo, ws, tid);
    __syncthreads();
    {
        float acc[4][4] = {};
#pragma unroll 4
        for (int d4 = 0; d4 < 64; d4 += 4) {
            float4 a[4], w[4];
#pragma unroll
            for (int i = 0; i < 4; ++i) a[i] = *(const float4*)&xs[(4 * tn + i) * LDSF + d4];
#pragma unroll
            for (int j = 0; j < 4; ++j) w[j] = *(const float4*)&ws[(4 * to + j) * LDSF + d4];
            fma16(acc, a, w);
        }
        float bj[4];
#pragma unroll
        for (int j = 0; j < 4; ++j) bj[j] = bo[4 * to + j];
#pragma unroll
        for (int i = 0; i < 4; ++i) {
            int row = 4 * tn + i;
            int tok = pg[row];
            float4 v;
            v.x = acc[i][0] + bj[0];
            v.y = acc[i][1] + bj[1];
            v.z = acc[i][2] + bj[2];
            v.w = acc[i][3] + bj[3];
            *(float4*)&out[((size_t)b * NTOK + tok) * DD + 4 * to] = v;
            *(float4*)&qs[row * LDSF + 4 * to] = v;  // stash for pooled max
        }
    }
    __syncthreads();
    if (tid < 64) {
        float m = qs[tid];
#pragma unroll 8
        for (int n = 1; n < 64; ++n) m = fmaxf(m, qs[n * LDSF + tid]);
        g_pooled[((size_t)b * GG + g) * DD + tid] = m;
    }
}

// ---------------- Kernel 2: inter QKV projections ----------------
// grid = 3*16*4 = 192 blocks: wsel = blk>>6, b = (blk>>2)&15, quarter = blk&3
__global__ __launch_bounds__(256) void inter_qkv_kernel(
    const float* __restrict__ Wq, const float* __restrict__ bq,
    const float* __restrict__ Wk, const float* __restrict__ bk,
    const float* __restrict__ Wv, const float* __restrict__ bv)
{
    __shared__ float As[64 * LDSF];
    __shared__ float ws[64 * LDSF];
    const int tid = threadIdx.x;
    const int blk = blockIdx.x;
    const int wsel = blk >> 6;
    const int b = (blk >> 2) & 15;
    const int quarter = blk & 3;
    const float* W = (wsel == 0) ? Wq : ((wsel == 1) ? Wk : Wv);
    const float* bias = (wsel == 0) ? bq : ((wsel == 1) ? bk : bv);
    const float* A = g_pooled + ((size_t)b * GG + quarter * 64) * DD;
    float* dst = g_qkv + ((size_t)(wsel * BB + b) * GG + quarter * 64) * DD;

#pragma unroll
    for (int k = 0; k < 4; ++k) {
        int f = tid + 256 * k;
        int r = f >> 4, c4 = f & 15;
        *(float4*)&As[r * LDSF + 4 * c4] = ((const float4*)(A + r * 64))[c4];
        *(float4*)&ws[r * LDSF + 4 * c4] = ((const float4*)(W + r * 64))[c4];
    }
    __syncthreads();

    const int tn = tid >> 4, to = tid & 15;
    float acc[4][4] = {};
#pragma unroll 4
    for (int d4 = 0; d4 < 64; d4 += 4) {
        float4 a[4], w[4];
#pragma unroll
        for (int i = 0; i < 4; ++i) a[i] = *(const float4*)&As[(4 * tn + i) * LDSF + d4];
#pragma unroll
        for (int j = 0; j < 4; ++j) w[j] = *(const float4*)&ws[(4 * to + j) * LDSF + d4];
        fma16(acc, a, w);
    }
    float bj[4];
#pragma unroll
    for (int j = 0; j < 4; ++j) bj[j] = bias[4 * to + j];
#pragma unroll
    for (int i = 0; i < 4; ++i) {
        float4 v;
        v.x = acc[i][0] + bj[0];
        v.y = acc[i][1] + bj[1];
        v.z = acc[i][2] + bj[2];
        v.w = acc[i][3] + bj[3];
        *(float4*)&dst[(4 * tn + i) * 64 + 4 * to] = v;
    }
}

// ---------------- Kernel 3: inter attention (+ O proj) ----------------
// grid = 16*16 = 256 blocks (b = blk>>4, token-chunk = blk&15), 128 threads
// dyn smem: K(256*LDSF) + V(256*LDSF) + probs(4*264) + q(64) + o(64) floats
__global__ __launch_bounds__(128) void inter_attn_kernel(
    const float* __restrict__ Wo, const float* __restrict__ bo)
{
    extern __shared__ float sm2[];
    float* ksm = sm2;
    float* vsm = sm2 + 256 * LDSF;
    float* ss  = sm2 + 2 * 256 * LDSF;  // 4 * 264
    float* sq  = ss + 4 * 264;          // 64
    float* so  = sq + 64;               // 64

    const int tid = threadIdx.x;
    const int b = blockIdx.x >> 4;
    const int chunk = blockIdx.x & 15;

    const float* qb = g_qkv + (size_t)(0 * BB + b) * GG * DD;
    const float* kb = g_qkv + (size_t)(1 * BB + b) * GG * DD;
    const float* vb = g_qkv + (size_t)(2 * BB + b) * GG * DD;

    // stage K and V for this batch: 4096 float4 each, 128 threads
#pragma unroll
    for (int k = 0; k < 32; ++k) {
        int f = tid + 128 * k;
        int row = f >> 4, c4 = f & 15;
        *(float4*)&ksm[row * LDSF + 4 * c4] = ((const float4*)(kb + row * 64))[c4];
        *(float4*)&vsm[row * LDSF + 4 * c4] = ((const float4*)(vb + row * 64))[c4];
    }
    __syncthreads();

    const int warp = tid >> 5, lane = tid & 31;

    for (int t0 = 0; t0 < 16; ++t0) {
        const int n = chunk * 16 + t0;
        if (tid < 64) sq[tid] = qb[n * 64 + tid];
        __syncthreads();

        // scores: one warp per head, 8 keys per lane (m = lane + 32k)
        const int hq = warp * 16;
        float4 q0 = *(const float4*)&sq[hq];
        float4 q1 = *(const float4*)&sq[hq + 4];
        float4 q2 = *(const float4*)&sq[hq + 8];
        float4 q3 = *(const float4*)&sq[hq + 12];
        float vals[8];
#pragma unroll
        for (int k = 0; k < 8; ++k) {
            int m = lane + 32 * k;
            const float* kr = ksm + m * LDSF + hq;
            float4 k0 = *(const float4*)kr;
            float4 k1 = *(const float4*)(kr + 4);
            float4 k2 = *(const float4*)(kr + 8);
            float4 k3 = *(const float4*)(kr + 12);
            float s = q0.x * k0.x + q0.y * k0.y + q0.z * k0.z + q0.w * k0.w
                    + q1.x * k1.x + q1.y * k1.y + q1.z * k1.z + q1.w * k1.w
                    + q2.x * k2.x + q2.y * k2.y + q2.z * k2.z + q2.w * k2.w
                    + q3.x * k3.x + q3.y * k3.y + q3.z * k3.z + q3.w * k3.w;
            vals[k] = 4.0f * s;
        }
        float mx = vals[0];
#pragma unroll
        for (int k = 1; k < 8; ++k) mx = fmaxf(mx, vals[k]);
#pragma unroll
        for (int off = 16; off; off >>= 1) mx = fmaxf(mx, __shfl_xor_sync(0xffffffffu, mx, off));
        float sum = 0.f;
#pragma unroll
        for (int k = 0; k < 8; ++k) { vals[k] = __expf(vals[k] - mx); sum += vals[k]; }
#pragma unroll
        for (int off = 16; off; off >>= 1) sum += __shfl_xor_sync(0xffffffffu, sum, off);
        float inv = 1.f / sum;
#pragma unroll
        for (int k = 0; k < 8; ++k) ss[warp * 264 + lane + 32 * k] = vals[k] * inv;
        __syncthreads();

        // AV: 64 threads -> (h, dd)
        if (tid < 64) {
            const int h = tid >> 4, dd = tid & 15;
            const float* pr = ss + h * 264;
            const float* vr = vsm + h * 16 + dd;
            float acc = 0.f;
#pragma unroll 8
            for (int m = 0; m < 256; ++m) acc = fmaf(pr[m], vr[m * LDSF], acc);
            so[tid] = acc;
        }
        __syncthreads();

        // O projection + bias
        if (tid < 64) {
            const float* wr = Wo + tid * 64;
            float acc = bo[tid];
#pragma unroll 8
            for (int d = 0; d < 64; ++d) acc = fmaf(so[d], wr[d], acc);
            g_inter[((size_t)b * GG + n) * DD + tid] = acc;
        }
        __syncthreads();
    }
}

// ---------------- Kernel 4: broadcast-add inter, scattered ----------------
// grid = 4096 (b*256+g), 256 threads
__global__ __launch_bounds__(256) void add_scatter_kernel(
    const int* __restrict__ part, float* __restrict__ out)
{
    __shared__ __align__(16) float iv[64];
    __shared__ int toks[64];
    const int tid = threadIdx.x;
    const int b = blockIdx.x >> 8;
    const int g = blockIdx.x & 255;
    if (tid < 64) iv[tid] = g_inter[((size_t)b * GG + g) * DD + tid];
    else if (tid < 128) toks[tid - 64] = part[(size_t)g * CC + (tid - 64)];
    __syncthreads();
#pragma unroll
    for (int k = 0; k < 4; ++k) {
        int f = tid + 256 * k;
        int row = f >> 4, c4 = f & 15;
        float* p = out + ((size_t)b * NTOK + toks[row]) * DD + 4 * c4;
        float4 v = *(float4*)p;
        float4 a = *(const float4*)&iv[4 * c4];
        v.x += a.x; v.y += a.y; v.z += a.z; v.w += a.w;
        *(float4*)p = v;
    }
}

// ---------------- launch ----------------
extern "C" void kernel_launch(void* const* d_in, const int* in_sizes, int n_in,
                              void* d_out, int out_size)
{
    (void)in_sizes; (void)n_in; (void)out_size;
    const float* x    = (const float*)d_in[0];
    const int*   part = (const int*)d_in[1];   // jnp int64 is demoted to int32 (x64 disabled)
    const float* Wq_a = (const float*)d_in[2];
    const float* bq_a = (const float*)d_in[3];
    const float* Wk_a = (const float*)d_in[4];
    const float* bk_a = (const float*)d_in[5];
    const float* Wv_a = (const float*)d_in[6];
    const float* bv_a = (const float*)d_in[7];
    const float* Wo_a = (const float*)d_in[8];
    const float* bo_a = (const float*)d_in[9];
    const float* Wq_i = (const float*)d_in[10];
    const float* bq_i = (const float*)d_in[11];
    const float* Wk_i = (const float*)d_in[12];
    const float* bk_i = (const float*)d_in[13];
    const float* Wv_i = (const float*)d_in[14];
    const float* bv_i = (const float*)d_in[15];
    const float* Wo_i = (const float*)d_in[16];
    const float* bo_i = (const float*)d_in[17];
    float* out = (float*)d_out;

    const int smem_intra = 5 * 64 * LDSF * (int)sizeof(float);                 // 87040 B
    const int smem_iatt  = (2 * 256 * LDSF + 4 * 264 + 128) * (int)sizeof(float); // 144000 B
    cudaFuncSetAttribute(intra_kernel, cudaFuncAttributeMaxDynamicSharedMemorySize, smem_intra);
    cudaFuncSetAttribute(inter_attn_kernel, cudaFuncAttributeMaxDynamicSharedMemorySize, smem_iatt);

    intra_kernel<<<BB * GG, 256, smem_intra>>>(x, part,
        Wq_a, bq_a, Wk_a, bk_a, Wv_a, bv_a, Wo_a, bo_a, out);
    inter_qkv_kernel<<<192, 256>>>(Wq_i, bq_i, Wk_i, bk_i, Wv_i, bv_i);
    inter_attn_kernel<<<256, 128, smem_iatt>>>(Wo_i, bo_i);
    add_scatter_kernel<<<BB * GG, 256>>>(part, out);
}

// round 5
// speedup vs baseline: 2.1723x; 2.1723x over previous
#include <cuda_runtime.h>
#include <cstdint>

// Problem constants (fixed by the dataset)
constexpr int BB   = 16;     // batch
constexpr int NTOK = 16384;  // tokens
constexpr int DD   = 64;     // model dim (= dhf)
constexpr int GG   = 256;    // groups
constexpr int CC   = 64;     // tokens per group
constexpr int NH   = 4;      // heads
// SCALE = sqrt(16) = 4.0 multiplies the scores (per reference)

#define LDSF 68  // smem row stride in floats

// ---------------- scratch (no allocations allowed) ----------------
__device__ float g_pooled[BB * GG * DD];      // 1 MiB
__device__ float g_qkv[3 * BB * GG * DD];     // 3 MiB  [q/k/v][b][n][d]
__device__ float g_inter[BB * GG * DD];       // 1 MiB

// ---------------- tf32 mma helpers ----------------
__device__ __forceinline__ uint32_t tf32r(float f) {
    uint32_t u; asm("cvt.rna.tf32.f32 %0, %1;" : "=r"(u) : "f"(f)); return u;
}
__device__ __forceinline__ float tf32f(float f) { return __uint_as_float(tf32r(f)); }

__device__ __forceinline__ void mma8(float c[4],
    uint32_t a0, uint32_t a1, uint32_t a2, uint32_t a3, uint32_t b0, uint32_t b1) {
    asm("mma.sync.aligned.m16n8k8.row.col.f32.tf32.tf32.f32 "
        "{%0,%1,%2,%3}, {%4,%5,%6,%7}, {%8,%9}, {%0,%1,%2,%3};"
        : "+f"(c[0]), "+f"(c[1]), "+f"(c[2]), "+f"(c[3])
        : "r"(a0), "r"(a1), "r"(a2), "r"(a3), "r"(b0), "r"(b1));
}
__device__ __forceinline__ uint32_t uf(float f) { return __float_as_uint(f); }

// copy 64x64 row-major matrix into smem (LDSF stride), tf32-rounded; 256 threads
__device__ __forceinline__ void stage64cvt(const float* __restrict__ W, float* ws, int tid) {
#pragma unroll
    for (int k = 0; k < 4; ++k) {
        int f = tid + 256 * k;      // float4 index 0..1023
        int r = f >> 4, c4 = f & 15;
        float4 v = ((const float4*)(W + r * 64))[c4];
        v.x = tf32f(v.x); v.y = tf32f(v.y); v.z = tf32f(v.z); v.w = tf32f(v.w);
        *(float4*)&ws[r * LDSF + 4 * c4] = v;
    }
}

// ---------------- Kernel 1: intra-group MHA (tf32 tensor cores) ----------------
// grid = 4096 (b*256+g), 256 threads = 8 warps, dyn smem = 5*64*LDSF*4 bytes
__global__ __launch_bounds__(256, 2) void intra_kernel(
    const float* __restrict__ x, const int* __restrict__ part,
    const float* __restrict__ Wq, const float* __restrict__ bq,
    const float* __restrict__ Wk, const float* __restrict__ bk,
    const float* __restrict__ Wv, const float* __restrict__ bv,
    const float* __restrict__ Wo, const float* __restrict__ bo,
    float* __restrict__ out)
{
    extern __shared__ float sm[];
    float* xs = sm;                 // tf32 x, later tf32 attention output
    float* qs = sm + 64 * LDSF;     // tf32 q, later fp32 final stash (pooled max)
    float* ks = sm + 2 * 64 * LDSF; // tf32 k
    float* vs = sm + 3 * 64 * LDSF; // tf32 v
    float* ws = sm + 4 * 64 * LDSF; // tf32 weight stage / scores+probs

    const int tid = threadIdx.x;
    const int bb = blockIdx.x >> 8;
    const int g  = blockIdx.x & 255;
    const int* pg = part + (size_t)g * CC;
    const float* xb = x + (size_t)bb * NTOK * DD;

    // gather 64 token rows (tf32-rounded)
#pragma unroll
    for (int k = 0; k < 4; ++k) {
        int f = tid + 256 * k;
        int row = f >> 4, c4 = f & 15;
        int tok = pg[row];
        float4 v = ((const float4*)(xb + (size_t)tok * DD))[c4];
        v.x = tf32f(v.x); v.y = tf32f(v.y); v.z = tf32f(v.z); v.w = tf32f(v.w);
        *(float4*)&xs[row * LDSF + 4 * c4] = v;
    }

    const int lane = tid & 31, w = tid >> 5;
    const int mt = w & 3;        // m-tile: rows 16*mt
    const int nq = w >> 2;       // n-half: cols 32*nq
    const int r  = lane >> 2;    // fragment group id (0..7)
    const int cc = lane & 3;     // thread-in-group (0..3)
    const int row0 = 16 * mt + r;
    const int c2 = 2 * cc;

    // ---- Q, K, V projections: D = xs @ W^T + b ----
    {
        const float* Wm[3] = {Wq, Wk, Wv};
        const float* bm[3] = {bq, bk, bv};
        float* Dm[3] = {qs, ks, vs};
#pragma unroll 1
        for (int s = 0; s < 3; ++s) {
            __syncthreads();
            stage64cvt(Wm[s], ws, tid);
            __syncthreads();
            float acc[4][4] = {};
#pragma unroll
            for (int kt = 0; kt < 8; ++kt) {
                const int k0 = 8 * kt;
                const float* ax = xs + row0 * LDSF + k0 + cc;
                uint32_t a0 = uf(ax[0]), a1 = uf(ax[8 * LDSF]);
                uint32_t a2 = uf(ax[4]), a3 = uf(ax[8 * LDSF + 4]);
#pragma unroll
                for (int nt = 0; nt < 4; ++nt) {
                    const int n0 = 32 * nq + 8 * nt;
                    const float* bx = ws + (n0 + r) * LDSF + k0 + cc;
                    mma8(acc[nt], a0, a1, a2, a3, uf(bx[0]), uf(bx[4]));
                }
            }
            float* D = Dm[s];
            const float* bia = bm[s];
#pragma unroll
            for (int nt = 0; nt < 4; ++nt) {
                const int n0 = 32 * nq + 8 * nt;
                float b0v = bia[n0 + c2], b1v = bia[n0 + c2 + 1];
                D[row0 * LDSF + n0 + c2]           = tf32f(acc[nt][0] + b0v);
                D[row0 * LDSF + n0 + c2 + 1]       = tf32f(acc[nt][1] + b1v);
                D[(row0 + 8) * LDSF + n0 + c2]     = tf32f(acc[nt][2] + b0v);
                D[(row0 + 8) * LDSF + n0 + c2 + 1] = tf32f(acc[nt][3] + b1v);
            }
        }
    }

    // ---- attention, head by head (scores/probs in ws; output into xs) ----
#pragma unroll 1
    for (int h = 0; h < NH; ++h) {
        const int hq = h * 16;
        __syncthreads();  // ws free
        // scores S = 4 * Q_h @ K_h^T
        {
            float acc[4][4] = {};
#pragma unroll
            for (int kt = 0; kt < 2; ++kt) {
                const int k0 = hq + 8 * kt;
                const float* ax = qs + row0 * LDSF + k0 + cc;
                uint32_t a0 = uf(ax[0]), a1 = uf(ax[8 * LDSF]);
                uint32_t a2 = uf(ax[4]), a3 = uf(ax[8 * LDSF + 4]);
#pragma unroll
                for (int nt = 0; nt < 4; ++nt) {
                    const int n0 = 32 * nq + 8 * nt;
                    const float* bx = ks + (n0 + r) * LDSF + k0 + cc;
                    mma8(acc[nt], a0, a1, a2, a3, uf(bx[0]), uf(bx[4]));
                }
            }
#pragma unroll
            for (int nt = 0; nt < 4; ++nt) {
                const int n0 = 32 * nq + 8 * nt;
                ws[row0 * LDSF + n0 + c2]           = 4.0f * acc[nt][0];
                ws[row0 * LDSF + n0 + c2 + 1]       = 4.0f * acc[nt][1];
                ws[(row0 + 8) * LDSF + n0 + c2]     = 4.0f * acc[nt][2];
                ws[(row0 + 8) * LDSF + n0 + c2 + 1] = 4.0f * acc[nt][3];
            }
        }
        __syncthreads();
        // softmax: 4 threads per row, quad shuffles; store tf32 probs
        {
            int row = tid >> 2, seg = tid & 3;
            float* rr = ws + row * LDSF + seg * 16;
            float mx = rr[0];
#pragma unroll
            for (int m = 1; m < 16; ++m) mx = fmaxf(mx, rr[m]);
            mx = fmaxf(mx, __shfl_xor_sync(0xffffffffu, mx, 1));
            mx = fmaxf(mx, __shfl_xor_sync(0xffffffffu, mx, 2));
            float e[16];
            float sum = 0.f;
#pragma unroll
            for (int m = 0; m < 16; ++m) { e[m] = __expf(rr[m] - mx); sum += e[m]; }
            sum += __shfl_xor_sync(0xffffffffu, sum, 1);
            sum += __shfl_xor_sync(0xffffffffu, sum, 2);
            float inv = 1.f / sum;
#pragma unroll
            for (int m = 0; m < 16; ++m) rr[m] = tf32f(e[m] * inv);
        }
        __syncthreads();
        // AV: O_h = P @ V_h. warp -> tile (mt, nq): rows 16mt.., cols hq+8nq..
        {
            float oacc[4] = {};
#pragma unroll
            for (int kt = 0; kt < 8; ++kt) {
                const int k0 = 8 * kt;
                const float* ax = ws + row0 * LDSF + k0 + cc;
                uint32_t a0 = uf(ax[0]), a1 = uf(ax[8 * LDSF]);
                uint32_t a2 = uf(ax[4]), a3 = uf(ax[8 * LDSF + 4]);
                const float* bx = vs + (k0 + cc) * LDSF + hq + 8 * nq + r;
                mma8(oacc, a0, a1, a2, a3, uf(bx[0]), uf(bx[4 * LDSF]));
            }
            const int n0 = hq + 8 * nq;
            xs[row0 * LDSF + n0 + c2]           = tf32f(oacc[0]);
            xs[row0 * LDSF + n0 + c2 + 1]       = tf32f(oacc[1]);
            xs[(row0 + 8) * LDSF + n0 + c2]     = tf32f(oacc[2]);
            xs[(row0 + 8) * LDSF + n0 + c2 + 1] = tf32f(oacc[3]);
        }
    }

    // ---- O projection (+bias), scatter to out, pooled max ----
    __syncthreads();
    stage64cvt(Wo, ws, tid);
    __syncthreads();
    {
        float acc[4][4] = {};
#pragma unroll
        for (int kt = 0; kt < 8; ++kt) {
            const int k0 = 8 * kt;
            const float* ax = xs + row0 * LDSF + k0 + cc;
            uint32_t a0 = uf(ax[0]), a1 = uf(ax[8 * LDSF]);
            uint32_t a2 = uf(ax[4]), a3 = uf(ax[8 * LDSF + 4]);
#pragma unroll
            for (int nt = 0; nt < 4; ++nt) {
                const int n0 = 32 * nq + 8 * nt;
                const float* bx = ws + (n0 + r) * LDSF + k0 + cc;
                mma8(acc[nt], a0, a1, a2, a3, uf(bx[0]), uf(bx[4]));
            }
        }
        const int tokA = pg[row0], tokB = pg[row0 + 8];
        float* oA = out + ((size_t)bb * NTOK + tokA) * DD;
        float* oB = out + ((size_t)bb * NTOK + tokB) * DD;
#pragma unroll
        for (int nt = 0; nt < 4; ++nt) {
            const int n0 = 32 * nq + 8 * nt;
            float b0v = bo[n0 + c2], b1v = bo[n0 + c2 + 1];
            float v0 = acc[nt][0] + b0v, v1 = acc[nt][1] + b1v;
            float v2 = acc[nt][2] + b0v, v3 = acc[nt][3] + b1v;
            *(float2*)(oA + n0 + c2) = make_float2(v0, v1);
            *(float2*)(oB + n0 + c2) = make_float2(v2, v3);
            *(float2*)&qs[row0 * LDSF + n0 + c2]       = make_float2(v0, v1);
            *(float2*)&qs[(row0 + 8) * LDSF + n0 + c2] = make_float2(v2, v3);
        }
    }
    __syncthreads();
    if (tid < 64) {
        float m = qs[tid];
#pragma unroll 8
        for (int n = 1; n < 64; ++n) m = fmaxf(m, qs[n * LDSF + tid]);
        g_pooled[((size_t)bb * GG + g) * DD + tid] = m;
    }
}

// ---------------- helpers for fp32 inter path ----------------
__device__ __forceinline__ void fma16(float acc[4][4], const float4 a[4], const float4 w[4]) {
#pragma unroll
    for (int i = 0; i < 4; ++i)
#pragma unroll
        for (int j = 0; j < 4; ++j) {
            acc[i][j] = fmaf(a[i].x, w[j].x, acc[i][j]);
            acc[i][j] = fmaf(a[i].y, w[j].y, acc[i][j]);
            acc[i][j] = fmaf(a[i].z, w[j].z, acc[i][j]);
            acc[i][j] = fmaf(a[i].w, w[j].w, acc[i][j]);
        }
}

// ---------------- Kernel 2: inter QKV projections ----------------
// grid = 3*16*4 = 192 blocks: wsel = blk>>6, b = (blk>>2)&15, quarter = blk&3
__global__ __launch_bounds__(256) void inter_qkv_kernel(
    const float* __restrict__ Wq, const float* __restrict__ bq,
    const float* __restrict__ Wk, const float* __restrict__ bk,
    const float* __restrict__ Wv, const float* __restrict__ bv)
{
    __shared__ float As[64 * LDSF];
    __shared__ float ws[64 * LDSF];
    const int tid = threadIdx.x;
    const int blk = blockIdx.x;
    const int wsel = blk >> 6;
    const int b = (blk >> 2) & 15;
    const int quarter = blk & 3;
    const float* W = (wsel == 0) ? Wq : ((wsel == 1) ? Wk : Wv);
    const float* bias = (wsel == 0) ? bq : ((wsel == 1) ? bk : bv);
    const float* A = g_pooled + ((size_t)b * GG + quarter * 64) * DD;
    float* dst = g_qkv + ((size_t)(wsel * BB + b) * GG + quarter * 64) * DD;

#pragma unroll
    for (int k = 0; k < 4; ++k) {
        int f = tid + 256 * k;
        int r = f >> 4, c4 = f & 15;
        *(float4*)&As[r * LDSF + 4 * c4] = ((const float4*)(A + r * 64))[c4];
        *(float4*)&ws[r * LDSF + 4 * c4] = ((const float4*)(W + r * 64))[c4];
    }
    __syncthreads();

    const int tn = tid >> 4, to = tid & 15;
    float acc[4][4] = {};
#pragma unroll 4
    for (int d4 = 0; d4 < 64; d4 += 4) {
        float4 a[4], w[4];
#pragma unroll
        for (int i = 0; i < 4; ++i) a[i] = *(const float4*)&As[(4 * tn + i) * LDSF + d4];
#pragma unroll
        for (int j = 0; j < 4; ++j) w[j] = *(const float4*)&ws[(4 * to + j) * LDSF + d4];
        fma16(acc, a, w);
    }
    float bj[4];
#pragma unroll
    for (int j = 0; j < 4; ++j) bj[j] = bias[4 * to + j];
#pragma unroll
    for (int i = 0; i < 4; ++i) {
        float4 v;
        v.x = acc[i][0] + bj[0];
        v.y = acc[i][1] + bj[1];
        v.z = acc[i][2] + bj[2];
        v.w = acc[i][3] + bj[3];
        *(float4*)&dst[(4 * tn + i) * 64 + 4 * to] = v;
    }
}

// ---------------- Kernel 3: inter attention (+ O proj) ----------------
// grid = 16*16 = 256 blocks (b = blk>>4, token-chunk = blk&15), 128 threads
__global__ __launch_bounds__(128) void inter_attn_kernel(
    const float* __restrict__ Wo, const float* __restrict__ bo)
{
    extern __shared__ float sm2[];
    float* ksm = sm2;
    float* vsm = sm2 + 256 * LDSF;
    float* ss  = sm2 + 2 * 256 * LDSF;  // 4 * 264
    float* sq  = ss + 4 * 264;          // 64
    float* so  = sq + 64;               // 64

    const int tid = threadIdx.x;
    const int b = blockIdx.x >> 4;
    const int chunk = blockIdx.x & 15;

    const float* qb = g_qkv + (size_t)(0 * BB + b) * GG * DD;
    const float* kb = g_qkv + (size_t)(1 * BB + b) * GG * DD;
    const float* vb = g_qkv + (size_t)(2 * BB + b) * GG * DD;

#pragma unroll
    for (int k = 0; k < 32; ++k) {
        int f = tid + 128 * k;
        int row = f >> 4, c4 = f & 15;
        *(float4*)&ksm[row * LDSF + 4 * c4] = ((const float4*)(kb + row * 64))[c4];
        *(float4*)&vsm[row * LDSF + 4 * c4] = ((const float4*)(vb + row * 64))[c4];
    }
    __syncthreads();

    const int warp = tid >> 5, lane = tid & 31;

    for (int t0 = 0; t0 < 16; ++t0) {
        const int n = chunk * 16 + t0;
        if (tid < 64) sq[tid] = qb[n * 64 + tid];
        __syncthreads();

        const int hq = warp * 16;
        float4 q0 = *(const float4*)&sq[hq];
        float4 q1 = *(const float4*)&sq[hq + 4];
        float4 q2 = *(const float4*)&sq[hq + 8];
        float4 q3 = *(const float4*)&sq[hq + 12];
        float vals[8];
#pragma unroll
        for (int k = 0; k < 8; ++k) {
            int m = lane + 32 * k;
            const float* kr = ksm + m * LDSF + hq;
            float4 k0 = *(const float4*)kr;
            float4 k1 = *(const float4*)(kr + 4);
            float4 k2 = *(const float4*)(kr + 8);
            float4 k3 = *(const float4*)(kr + 12);
            float s = q0.x * k0.x + q0.y * k0.y + q0.z * k0.z + q0.w * k0.w
                    + q1.x * k1.x + q1.y * k1.y + q1.z * k1.z + q1.w * k1.w
                    + q2.x * k2.x + q2.y * k2.y + q2.z * k2.z + q2.w * k2.w
                    + q3.x * k3.x + q3.y * k3.y + q3.z * k3.z + q3.w * k3.w;
            vals[k] = 4.0f * s;
        }
        float mx = vals[0];
#pragma unroll
        for (int k = 1; k < 8; ++k) mx = fmaxf(mx, vals[k]);
#pragma unroll
        for (int off = 16; off; off >>= 1) mx = fmaxf(mx, __shfl_xor_sync(0xffffffffu, mx, off));
        float sum = 0.f;
#pragma unroll
        for (int k = 0; k < 8; ++k) { vals[k] = __expf(vals[k] - mx); sum += vals[k]; }
#pragma unroll
        for (int off = 16; off; off >>= 1) sum += __shfl_xor_sync(0xffffffffu, sum, off);
        float inv = 1.f / sum;
#pragma unroll
        for (int k = 0; k < 8; ++k) ss[warp * 264 + lane + 32 * k] = vals[k] * inv;
        __syncthreads();

        if (tid < 64) {
            const int h = tid >> 4, dd = tid & 15;
            const float* pr = ss + h * 264;
            const float* vr = vsm + h * 16 + dd;
            float acc = 0.f;
#pragma unroll 8
            for (int m = 0; m < 256; ++m) acc = fmaf(pr[m], vr[m * LDSF], acc);
            so[tid] = acc;
        }
        __syncthreads();

        if (tid < 64) {
            const float* wr = Wo + tid * 64;
            float acc = bo[tid];
#pragma unroll 8
            for (int d = 0; d < 64; ++d) acc = fmaf(so[d], wr[d], acc);
            g_inter[((size_t)b * GG + n) * DD + tid] = acc;
        }
        __syncthreads();
    }
}

// ---------------- Kernel 4: broadcast-add inter, scattered ----------------
// grid = 4096 (b*256+g), 256 threads
__global__ __launch_bounds__(256) void add_scatter_kernel(
    const int* __restrict__ part, float* __restrict__ out)
{
    __shared__ __align__(16) float iv[64];
    __shared__ int toks[64];
    const int tid = threadIdx.x;
    const int b = blockIdx.x >> 8;
    const int g = blockIdx.x & 255;
    if (tid < 64) iv[tid] = g_inter[((size_t)b * GG + g) * DD + tid];
    else if (tid < 128) toks[tid - 64] = part[(size_t)g * CC + (tid - 64)];
    __syncthreads();
#pragma unroll
    for (int k = 0; k < 4; ++k) {
        int f = tid + 256 * k;
        int row = f >> 4, c4 = f & 15;
        float* p = out + ((size_t)b * NTOK + toks[row]) * DD + 4 * c4;
        float4 v = *(float4*)p;
        float4 a = *(const float4*)&iv[4 * c4];
        v.x += a.x; v.y += a.y; v.z += a.z; v.w += a.w;
        *(float4*)p = v;
    }
}

// ---------------- launch ----------------
extern "C" void kernel_launch(void* const* d_in, const int* in_sizes, int n_in,
                              void* d_out, int out_size)
{
    (void)in_sizes; (void)n_in; (void)out_size;
    const float* x    = (const float*)d_in[0];
    const int*   part = (const int*)d_in[1];   // int32 on device (JAX x64 disabled)
    const float* Wq_a = (const float*)d_in[2];
    const float* bq_a = (const float*)d_in[3];
    const float* Wk_a = (const float*)d_in[4];
    const float* bk_a = (const float*)d_in[5];
    const float* Wv_a = (const float*)d_in[6];
    const float* bv_a = (const float*)d_in[7];
    const float* Wo_a = (const float*)d_in[8];
    const float* bo_a = (const float*)d_in[9];
    const float* Wq_i = (const float*)d_in[10];
    const float* bq_i = (const float*)d_in[11];
    const float* Wk_i = (const float*)d_in[12];
    const float* bk_i = (const float*)d_in[13];
    const float* Wv_i = (const float*)d_in[14];
    const float* bv_i = (const float*)d_in[15];
    const float* Wo_i = (const float*)d_in[16];
    const float* bo_i = (const float*)d_in[17];
    float* out = (float*)d_out;

    const int smem_intra = 5 * 64 * LDSF * (int)sizeof(float);                 // 87040 B
    const int smem_iatt  = (2 * 256 * LDSF + 4 * 264 + 128) * (int)sizeof(float); // 144000 B
    cudaFuncSetAttribute(intra_kernel, cudaFuncAttributeMaxDynamicSharedMemorySize, smem_intra);
    cudaFuncSetAttribute(inter_attn_kernel, cudaFuncAttributeMaxDynamicSharedMemorySize, smem_iatt);

    intra_kernel<<<BB * GG, 256, smem_intra>>>(x, part,
        Wq_a, bq_a, Wk_a, bk_a, Wv_a, bv_a, Wo_a, bo_a, out);
    inter_qkv_kernel<<<192, 256>>>(Wq_i, bq_i, Wk_i, bk_i, Wv_i, bv_i);
    inter_attn_kernel<<<256, 128, smem_iatt>>>(Wo_i, bo_i);
    add_scatter_kernel<<<BB * GG, 256>>>(part, out);
}